// round 2
// baseline (speedup 1.0000x reference)
#include <cuda_runtime.h>
#include <cuda_bf16.h>
#include <cstdint>
#include <cstddef>

#define T_STEPS 100
#define BATCH   256
#define HID     1024
#define N_IN    4096
#define NQ      2048

#define NCTA   64
#define BTILE  64
#define HTILE  64
#define KCHUNK 128
#define SW     1032   // Wm smem row stride (bf16 elems), 2064B -> conflict-free ldmatrix
#define AW     136    // A smem row stride (bf16 elems), 272B
#define XW     68     // xs smem row stride (floats)

// ---------------- device scratch (static, no allocations) ----------------
__device__ __nv_bfloat16 g_Wm[HID * HID];                      // bf16 Wm
__device__ float         g_WxT[(size_t)N_IN * HID];            // Wx transposed
__device__ float         g_bias[HID];                          // bm + bx
__device__ __nv_bfloat16 g_hidden[(size_t)(T_STEPS + 1) * BATCH * HID]; // h history
__device__ unsigned      g_count;                              // barrier arrive count
__device__ unsigned      g_gen;                                // barrier generation

// ---------------- small PTX helpers ----------------
__device__ __forceinline__ uint32_t smem_u32(const void* p) {
    return (uint32_t)__cvta_generic_to_shared(p);
}
__device__ __forceinline__ void ldmx4(uint32_t& r0, uint32_t& r1, uint32_t& r2, uint32_t& r3,
                                      uint32_t addr) {
    asm volatile("ldmatrix.sync.aligned.m8n8.x4.shared.b16 {%0,%1,%2,%3},[%4];\n"
                 : "=r"(r0), "=r"(r1), "=r"(r2), "=r"(r3) : "r"(addr));
}
__device__ __forceinline__ void mma16816(float* c, uint32_t a0, uint32_t a1, uint32_t a2,
                                         uint32_t a3, uint32_t b0, uint32_t b1) {
    asm volatile("mma.sync.aligned.m16n8k16.row.col.f32.bf16.bf16.f32 "
                 "{%0,%1,%2,%3},{%4,%5,%6,%7},{%8,%9},{%0,%1,%2,%3};\n"
                 : "+f"(c[0]), "+f"(c[1]), "+f"(c[2]), "+f"(c[3])
                 : "r"(a0), "r"(a1), "r"(a2), "r"(a3), "r"(b0), "r"(b1));
}
__device__ __forceinline__ void cp16(uint32_t dst, const void* src) {
    asm volatile("cp.async.cg.shared.global [%0],[%1],16;\n" :: "r"(dst), "l"(src));
}

// ---------------- prologue: Wm->bf16, bias fold, h0 init ----------------
__global__ void prep_kernel(const float* __restrict__ Wm, const float* __restrict__ bm,
                            const float* __restrict__ bx, const float* __restrict__ b_start) {
    int i = blockIdx.x * blockDim.x + threadIdx.x;
    int stride = gridDim.x * blockDim.x;
    for (int k = i; k < HID * HID; k += stride)
        g_Wm[k] = __float2bfloat16(Wm[k]);
    for (int k = i; k < HID; k += stride)
        g_bias[k] = bm[k] + bx[k];
    for (int k = i; k < BATCH * HID; k += stride)
        g_hidden[k] = __float2bfloat16(b_start[k & (HID - 1)]);  // h0 = b_start broadcast
}

// ---------------- prologue: transpose Wx [H, NIN] -> WxT [NIN, H] ----------------
__global__ void transpose_wx(const float* __restrict__ Wx) {
    __shared__ float tile[32][33];
    int x0 = blockIdx.x * 32;   // along N_IN
    int y0 = blockIdx.y * 32;   // along HID
    int tx = threadIdx.x;
    for (int i = threadIdx.y; i < 32; i += 8)
        tile[i][tx] = Wx[(size_t)(y0 + i) * N_IN + x0 + tx];
    __syncthreads();
    for (int i = threadIdx.y; i < 32; i += 8)
        g_WxT[(size_t)(x0 + i) * HID + y0 + tx] = tile[tx][i];
}

// ---------------- persistent RNN mainloop ----------------
__global__ void __launch_bounds__(128, 1) rnn_kernel(const int* __restrict__ x_idx) {
    extern __shared__ char smem_raw[];
    __nv_bfloat16* wm_s  = (__nv_bfloat16*)smem_raw;          // 64 x SW bf16 (resident Wm slab)
    __nv_bfloat16* a_s   = wm_s + HTILE * SW;                 // 2 x 64 x AW bf16 (h tile, dbuf)
    float*         xs    = (float*)(a_s + 2 * BTILE * AW);    // 64 x XW floats (x gather)
    float*         bias_s = xs + BTILE * XW;                  // 64 floats

    const int tid  = threadIdx.x;
    const int warp = tid >> 5, lane = tid & 31;
    const int bi = blockIdx.x & 3;      // batch tile (4)
    const int hj = blockIdx.x >> 2;     // hidden tile (16)
    const int b0g = bi * BTILE;
    const int h0g = hj * HTILE;

    // Load Wm slab rows [h0g, h0g+64) into SMEM once — reused for all 100 steps.
    for (int i = tid; i < HTILE * 128; i += 128) {
        int r = i >> 7, c = i & 127;
        uint4 v = *(const uint4*)&g_Wm[(size_t)(h0g + r) * HID + c * 8];
        *(uint4*)&wm_s[r * SW + c * 8] = v;
    }
    if (tid < HTILE) bias_s[tid] = g_bias[h0g + tid];
    __syncthreads();

    const int lane_r = lane & 15;
    const int lane_c8 = (lane >> 4) << 3;
    const uint32_t a_addr0  = smem_u32(a_s) + (uint32_t)(((warp * 16 + lane_r) * AW + lane_c8) * 2);
    const uint32_t wm_addr0 = smem_u32(wm_s) + (uint32_t)((lane_r * SW + lane_c8) * 2);

    for (int t = 0; t < T_STEPS; t++) {
        const __nv_bfloat16* hprev = g_hidden + (size_t)t * BATCH * HID;

        // gather x projection: xs[b][h] = WxT[x_idx[t,b]][h0g + h]
        {
            int b = tid >> 1, half = tid & 1;
            int x = x_idx[t * BATCH + b0g + b];
            const float4* src = (const float4*)&g_WxT[(size_t)x * HID + h0g + half * 32];
            float4* dst = (float4*)&xs[b * XW + half * 32];
            #pragma unroll
            for (int q = 0; q < 8; q++) dst[q] = src[q];
        }

        float acc[8][4];
        #pragma unroll
        for (int n = 0; n < 8; n++) { acc[n][0] = acc[n][1] = acc[n][2] = acc[n][3] = 0.f; }

        // prefetch K-chunk 0 of the h tile
        #pragma unroll
        for (int q = 0; q < 8; q++) {
            int idx = tid + q * 128;
            int r = idx >> 4, c16 = idx & 15;
            cp16(smem_u32(&a_s[r * AW + c16 * 8]), &hprev[(size_t)(b0g + r) * HID + c16 * 8]);
        }
        asm volatile("cp.async.commit_group;\n");

        for (int ch = 0; ch < 8; ch++) {
            if (ch < 7) {
                const __nv_bfloat16* base = hprev + (ch + 1) * KCHUNK;
                __nv_bfloat16* abuf = a_s + ((ch + 1) & 1) * BTILE * AW;
                #pragma unroll
                for (int q = 0; q < 8; q++) {
                    int idx = tid + q * 128;
                    int r = idx >> 4, c16 = idx & 15;
                    cp16(smem_u32(&abuf[r * AW + c16 * 8]),
                         &base[(size_t)(b0g + r) * HID + c16 * 8]);
                }
                asm volatile("cp.async.commit_group;\n");
                asm volatile("cp.async.wait_group 1;\n");
            } else {
                asm volatile("cp.async.wait_group 0;\n");
            }
            __syncthreads();

            uint32_t abase = a_addr0 + (uint32_t)((ch & 1) * BTILE * AW * 2);
            #pragma unroll
            for (int kk = 0; kk < KCHUNK; kk += 16) {
                uint32_t a0, a1, a2, a3;
                ldmx4(a0, a1, a2, a3, abase + kk * 2);
                uint32_t kcol = (uint32_t)((ch * KCHUNK + kk) * 2);
                #pragma unroll
                for (int p = 0; p < 4; p++) {
                    uint32_t b0, b1, b2, b3;
                    ldmx4(b0, b1, b2, b3, wm_addr0 + (uint32_t)(p * 16 * SW * 2) + kcol);
                    mma16816(acc[2 * p],     a0, a1, a2, a3, b0, b2);
                    mma16816(acc[2 * p + 1], a0, a1, a2, a3, b1, b3);
                }
            }
            __syncthreads();
        }

        // epilogue: +x, +bias, tanh, store bf16 h[t+1]
        __nv_bfloat16* hout = g_hidden + (size_t)(t + 1) * BATCH * HID;
        int mr = lane >> 2;
        int cp0 = (lane & 3) * 2;
        #pragma unroll
        for (int n = 0; n < 8; n++) {
            #pragma unroll
            for (int half = 0; half < 2; half++) {
                int row = warp * 16 + mr + half * 8;
                int col = n * 8 + cp0;
                float v0 = tanhf(acc[n][half * 2 + 0] + xs[row * XW + col]     + bias_s[col]);
                float v1 = tanhf(acc[n][half * 2 + 1] + xs[row * XW + col + 1] + bias_s[col + 1]);
                __nv_bfloat162 pack = __floats2bfloat162_rn(v0, v1);
                *(__nv_bfloat162*)&hout[(size_t)(b0g + row) * HID + h0g + col] = pack;
            }
        }

        // software grid barrier (all 64 CTAs co-resident: 1 CTA/SM at 180KB smem)
        __syncthreads();
        if (tid == 0) {
            __threadfence();
            unsigned gen = atomicAdd(&g_gen, 0u);
            unsigned old = atomicAdd(&g_count, 1u);
            if (old == NCTA - 1) {
                atomicExch(&g_count, 0u);
                __threadfence();
                atomicAdd(&g_gen, 1u);
            } else {
                while (*(volatile unsigned*)&g_gen == gen) { }
            }
            __threadfence();
        }
        __syncthreads();
    }
}

// ---------------- epilogue: logits / pred / loss ----------------
__global__ void logits_kernel(const int* __restrict__ y_idx, const float* __restrict__ truth,
                              const float* __restrict__ Wy, const float* __restrict__ by,
                              float* __restrict__ out) {
    int gw = (blockIdx.x * blockDim.x + threadIdx.x) >> 5;
    int lane = threadIdx.x & 31;
    if (gw >= T_STEPS * BATCH) return;
    int t = gw >> 8;
    int b = gw & 255;
    int y = y_idx[gw];
    const __nv_bfloat16* h = g_hidden + (size_t)(t + 1) * BATCH * HID + (size_t)b * HID;
    const float* wy = Wy + (size_t)y * HID;
    float acc = 0.f;
    #pragma unroll 4
    for (int k = lane; k < HID; k += 32)
        acc += __bfloat162float(h[k]) * wy[k];
    #pragma unroll
    for (int o = 16; o; o >>= 1) acc += __shfl_xor_sync(0xffffffffu, acc, o);
    if (lane == 0) {
        float logit = acc + by[y];
        float pred = 1.f / (1.f + expf(-logit));
        float tr = truth[gw];
        float lsp = fminf(logit, 0.f)  - log1pf(expf(-fabsf(logit)));   // log_sigmoid(logit)
        float lsn = fminf(-logit, 0.f) - log1pf(expf(-fabsf(logit)));   // log_sigmoid(-logit)
        float loss = -(tr * lsp + (1.f - tr) * lsn);
        out[gw] = pred;
        out[T_STEPS * BATCH + gw] = loss;
    }
}

// ---------------- launch ----------------
extern "C" void kernel_launch(void* const* d_in, const int* in_sizes, int n_in,
                              void* d_out, int out_size) {
    (void)in_sizes; (void)n_in; (void)out_size;
    const int*   x_idx   = (const int*)d_in[0];
    const int*   y_idx   = (const int*)d_in[1];
    const float* truth   = (const float*)d_in[2];
    const float* Wm      = (const float*)d_in[3];
    const float* bm      = (const float*)d_in[4];
    const float* Wx      = (const float*)d_in[5];
    const float* bx      = (const float*)d_in[6];
    const float* Wy      = (const float*)d_in[7];
    const float* by      = (const float*)d_in[8];
    // d_in[9] = W_start: multiplied by zeros in the reference -> unused
    const float* b_start = (const float*)d_in[10];
    float* out = (float*)d_out;

    prep_kernel<<<1024, 256>>>(Wm, bm, bx, b_start);
    transpose_wx<<<dim3(N_IN / 32, HID / 32), dim3(32, 8)>>>(Wx);

    const int smem_bytes = (HTILE * SW + 2 * BTILE * AW) * 2 + (BTILE * XW + HTILE) * 4;
    cudaFuncSetAttribute(rnn_kernel, cudaFuncAttributeMaxDynamicSharedMemorySize, smem_bytes);
    rnn_kernel<<<NCTA, 128, smem_bytes>>>(x_idx);

    logits_kernel<<<(T_STEPS * BATCH * 32 + 255) / 256, 256>>>(y_idx, truth, Wy, by, out);
}

// round 4
// speedup vs baseline: 1.2581x; 1.2581x over previous
#include <cuda_runtime.h>
#include <cuda_bf16.h>
#include <cstdint>
#include <cstddef>

#define T_STEPS 100
#define BATCH   256
#define HID     1024
#define N_IN    4096

#define NCTA   128
#define GROUPS 8           // batch groups (32 rows each) — independent sync domains
#define GSZ    16          // CTAs per group (N tiles)
#define MT     32          // batch rows per group
#define NT     64          // hidden cols per CTA
#define KC     256         // K chunk for staged cp.async
#define SW     1032        // smem row stride in bf16 (2064B -> conflict-free ldmatrix)
#define XW     68          // xs row stride in floats

// ---------------- device scratch ----------------
__device__ __nv_bfloat16 g_hidden[(size_t)(T_STEPS + 1) * BATCH * HID];
__device__ float         g_WxT[(size_t)N_IN * HID];   // Wx^T with (bm+bx) folded in
__device__ unsigned      g_count[GROUPS];
__device__ unsigned      g_gen[GROUPS];

// ---------------- helpers ----------------
__device__ __forceinline__ uint32_t smem_u32(const void* p) {
    return (uint32_t)__cvta_generic_to_shared(p);
}
__device__ __forceinline__ void ldmx4(uint32_t& r0, uint32_t& r1, uint32_t& r2, uint32_t& r3,
                                      uint32_t addr) {
    asm volatile("ldmatrix.sync.aligned.m8n8.x4.shared.b16 {%0,%1,%2,%3},[%4];\n"
                 : "=r"(r0), "=r"(r1), "=r"(r2), "=r"(r3) : "r"(addr));
}
__device__ __forceinline__ void mma16816(float* c, uint32_t a0, uint32_t a1, uint32_t a2,
                                         uint32_t a3, uint32_t b0, uint32_t b1) {
    asm volatile("mma.sync.aligned.m16n8k16.row.col.f32.bf16.bf16.f32 "
                 "{%0,%1,%2,%3},{%4,%5,%6,%7},{%8,%9},{%0,%1,%2,%3};\n"
                 : "+f"(c[0]), "+f"(c[1]), "+f"(c[2]), "+f"(c[3])
                 : "r"(a0), "r"(a1), "r"(a2), "r"(a3), "r"(b0), "r"(b1));
}
__device__ __forceinline__ void cp16(uint32_t dst, const void* src) {
    asm volatile("cp.async.cg.shared.global [%0],[%1],16;\n" :: "r"(dst), "l"(src));
}

// ---------------- prologue kernels ----------------
__global__ void prep_kernel(const float* __restrict__ b_start) {
    int i = blockIdx.x * blockDim.x + threadIdx.x;
    if (i < BATCH * HID)
        g_hidden[i] = __float2bfloat16(b_start[i & (HID - 1)]);  // h0 = b_start broadcast
}

__global__ void transpose_wx(const float* __restrict__ Wx, const float* __restrict__ bm,
                             const float* __restrict__ bx) {
    __shared__ float tile[32][33];
    int x0 = blockIdx.x * 32;   // along N_IN
    int y0 = blockIdx.y * 32;   // along HID
    int tx = threadIdx.x;
    for (int i = threadIdx.y; i < 32; i += 8)
        tile[i][tx] = Wx[(size_t)(y0 + i) * N_IN + x0 + tx];
    __syncthreads();
    for (int i = threadIdx.y; i < 32; i += 8)
        g_WxT[(size_t)(x0 + i) * HID + y0 + tx] = tile[tx][i] + bm[y0 + tx] + bx[y0 + tx];
}

// ---------------- persistent RNN mainloop (128 CTAs, per-group barriers) ----------------
__global__ void __launch_bounds__(128, 1) rnn_kernel(const int* __restrict__ x_idx,
                                                     const float* __restrict__ Wm) {
    extern __shared__ __align__(16) char smem_raw[];
    __nv_bfloat16* wm_s = (__nv_bfloat16*)smem_raw;       // 64 x SW bf16 (resident Wm slab)
    __nv_bfloat16* a_s  = wm_s + NT * SW;                 // 32 x SW bf16 (full h tile)
    float*         xs   = (float*)(a_s + MT * SW);        // 32 x XW floats

    const int tid  = threadIdx.x;
    const int warp = tid >> 5, lane = tid & 31;
    const int grp = blockIdx.x >> 4;      // batch group (8)
    const int nt  = blockIdx.x & 15;      // N tile within group (16)
    const int m0 = grp * MT;
    const int n0 = nt * NT;

    // Load Wm slab rows [n0, n0+64) x K=1024, f32 -> bf16, resident for all steps.
    for (int i = tid; i < NT * 128; i += 128) {
        int r = i >> 7, c8 = i & 127;
        const float4* s = (const float4*)&Wm[(size_t)(n0 + r) * HID + c8 * 8];
        float4 f0 = s[0], f1 = s[1];
        uint32_t pk[4];
        ((__nv_bfloat162*)pk)[0] = __floats2bfloat162_rn(f0.x, f0.y);
        ((__nv_bfloat162*)pk)[1] = __floats2bfloat162_rn(f0.z, f0.w);
        ((__nv_bfloat162*)pk)[2] = __floats2bfloat162_rn(f1.x, f1.y);
        ((__nv_bfloat162*)pk)[3] = __floats2bfloat162_rn(f1.z, f1.w);
        *(uint4*)&wm_s[r * SW + c8 * 8] = *(uint4*)pk;
    }
    __syncthreads();

    // ldmatrix lane bases (row = lane&15, k-half = lane>>4)
    const uint32_t a_lane = smem_u32(a_s) +
        (uint32_t)(((lane & 15) * SW + ((lane >> 4) << 3)) * 2);
    const uint32_t b_lane = smem_u32(wm_s) +
        (uint32_t)(((warp * 16 + (lane & 15)) * SW + ((lane >> 4) << 3)) * 2);

    for (int t = 0; t < T_STEPS; t++) {
        const __nv_bfloat16* hp = g_hidden + (size_t)t * BATCH * HID + (size_t)m0 * HID;

        // Issue all 4 K-chunks of the A tile (32 rows x 1024 cols), one commit per chunk.
        {
            const int r = tid >> 2, q4 = tid & 3;
            const __nv_bfloat16* rowp = hp + (size_t)r * HID;
            const uint32_t rowd = smem_u32(a_s) + (uint32_t)(r * SW * 2);
            #pragma unroll
            for (int ch = 0; ch < 4; ch++) {
                #pragma unroll
                for (int q = 0; q < 8; q++) {
                    int c8 = ch * 32 + q4 * 8 + q;
                    cp16(rowd + (uint32_t)(c8 * 16), rowp + c8 * 8);
                }
                asm volatile("cp.async.commit_group;" ::: "memory");
            }
        }

        // x projection gather (bias folded into g_WxT) — overlaps chunk waits
        {
            const int r = tid >> 2, seg = tid & 3;
            int x = x_idx[t * BATCH + m0 + r];
            const float4* src = (const float4*)&g_WxT[(size_t)x * HID + n0 + seg * 16];
            float4* dst = (float4*)&xs[r * XW + seg * 16];
            dst[0] = src[0]; dst[1] = src[1]; dst[2] = src[2]; dst[3] = src[3];
        }

        float acc[2][2][4];
        #pragma unroll
        for (int i = 0; i < 2; i++)
            #pragma unroll
            for (int j = 0; j < 2; j++)
                acc[i][j][0] = acc[i][j][1] = acc[i][j][2] = acc[i][j][3] = 0.f;

        #pragma unroll
        for (int ch = 0; ch < 4; ch++) {
            if (ch == 0)      asm volatile("cp.async.wait_group 3;" ::: "memory");
            else if (ch == 1) asm volatile("cp.async.wait_group 2;" ::: "memory");
            else if (ch == 2) asm volatile("cp.async.wait_group 1;" ::: "memory");
            else              asm volatile("cp.async.wait_group 0;" ::: "memory");
            __syncthreads();

            #pragma unroll
            for (int kk = 0; kk < KC; kk += 16) {
                const uint32_t kb = (uint32_t)((ch * KC + kk) * 2);
                uint32_t a0, a1, a2, a3, a4, a5, a6, a7, b0, b1, b2, b3;
                ldmx4(a0, a1, a2, a3, a_lane + kb);                        // rows 0-15
                ldmx4(a4, a5, a6, a7, a_lane + (uint32_t)(16 * SW * 2) + kb); // rows 16-31
                ldmx4(b0, b1, b2, b3, b_lane + kb);                        // n rows warp*16..+16
                mma16816(acc[0][0], a0, a1, a2, a3, b0, b2);
                mma16816(acc[0][1], a0, a1, a2, a3, b1, b3);
                mma16816(acc[1][0], a4, a5, a6, a7, b0, b2);
                mma16816(acc[1][1], a4, a5, a6, a7, b1, b3);
            }
        }

        // epilogue: + xproj(+bias), tanh.approx, pack bf16, store h[t+1]
        __nv_bfloat16* hout = g_hidden + (size_t)(t + 1) * BATCH * HID;
        const int r_base = lane >> 2;
        const int c_base = (lane & 3) * 2;
        #pragma unroll
        for (int mi = 0; mi < 2; mi++) {
            #pragma unroll
            for (int ni = 0; ni < 2; ni++) {
                int col = warp * 16 + ni * 8 + c_base;   // within CTA's 64
                #pragma unroll
                for (int half = 0; half < 2; half++) {
                    int row = mi * 16 + r_base + half * 8;
                    float v0 = acc[mi][ni][half * 2 + 0] + xs[row * XW + col];
                    float v1 = acc[mi][ni][half * 2 + 1] + xs[row * XW + col + 1];
                    asm("tanh.approx.f32 %0, %0;" : "+f"(v0));
                    asm("tanh.approx.f32 %0, %0;" : "+f"(v1));
                    *(__nv_bfloat162*)&hout[(size_t)(m0 + row) * HID + n0 + col] =
                        __floats2bfloat162_rn(v0, v1);
                }
            }
        }

        // per-group barrier (16 CTAs — independent sync domains per batch group)
        __syncthreads();
        if (tid == 0) {
            __threadfence();
            unsigned gen = atomicAdd(&g_gen[grp], 0u);
            unsigned old = atomicAdd(&g_count[grp], 1u);
            if (old == GSZ - 1) {
                atomicExch(&g_count[grp], 0u);
                __threadfence();
                atomicAdd(&g_gen[grp], 1u);
            } else {
                while (*(volatile unsigned*)&g_gen[grp] == gen) { }
            }
            __threadfence();
        }
        __syncthreads();
    }
}

// ---------------- epilogue: logits / pred / loss ----------------
__global__ void logits_kernel(const int* __restrict__ y_idx, const float* __restrict__ truth,
                              const float* __restrict__ Wy, const float* __restrict__ by,
                              float* __restrict__ out) {
    int gw = (blockIdx.x * blockDim.x + threadIdx.x) >> 5;
    int lane = threadIdx.x & 31;
    if (gw >= T_STEPS * BATCH) return;
    int t = gw >> 8;
    int b = gw & 255;
    int y = y_idx[gw];
    const __nv_bfloat16* h = g_hidden + (size_t)(t + 1) * BATCH * HID + (size_t)b * HID;
    const float* wy = Wy + (size_t)y * HID;
    float acc = 0.f;
    #pragma unroll 4
    for (int k = lane; k < HID; k += 32)
        acc += __bfloat162float(h[k]) * wy[k];
    #pragma unroll
    for (int o = 16; o; o >>= 1) acc += __shfl_xor_sync(0xffffffffu, acc, o);
    if (lane == 0) {
        float logit = acc + by[y];
        float pred = 1.f / (1.f + expf(-logit));
        float tr = truth[gw];
        float lsp = fminf(logit, 0.f)  - log1pf(expf(-fabsf(logit)));
        float lsn = fminf(-logit, 0.f) - log1pf(expf(-fabsf(logit)));
        float loss = -(tr * lsp + (1.f - tr) * lsn);
        out[gw] = pred;
        out[T_STEPS * BATCH + gw] = loss;
    }
}

// ---------------- launch ----------------
extern "C" void kernel_launch(void* const* d_in, const int* in_sizes, int n_in,
                              void* d_out, int out_size) {
    (void)in_sizes; (void)n_in; (void)out_size;
    const int*   x_idx   = (const int*)d_in[0];
    const int*   y_idx   = (const int*)d_in[1];
    const float* truth   = (const float*)d_in[2];
    const float* Wm      = (const float*)d_in[3];
    const float* bm      = (const float*)d_in[4];
    const float* Wx      = (const float*)d_in[5];
    const float* bx      = (const float*)d_in[6];
    const float* Wy      = (const float*)d_in[7];
    const float* by      = (const float*)d_in[8];
    // d_in[9] = W_start: multiplied by zeros -> unused
    const float* b_start = (const float*)d_in[10];
    float* out = (float*)d_out;

    prep_kernel<<<(BATCH * HID + 255) / 256, 256>>>(b_start);
    transpose_wx<<<dim3(N_IN / 32, HID / 32), dim3(32, 8)>>>(Wx, bm, bx);

    const int smem_bytes = (NT * SW + MT * SW) * 2 + MT * XW * 4;   // ~207 KB
    cudaFuncSetAttribute(rnn_kernel, cudaFuncAttributeMaxDynamicSharedMemorySize, smem_bytes);
    rnn_kernel<<<NCTA, 128, smem_bytes>>>(x_idx, Wm);

    logits_kernel<<<(T_STEPS * BATCH * 32 + 255) / 256, 256>>>(y_idx, truth, Wy, by, out);
}